// round 9
// baseline (speedup 1.0000x reference)
#include <cuda_runtime.h>

// SSIM over (64,1,512,512) f32, 11x11 zero-padded box filters.
// Separable box filter, R8 revision:
//   - Horizontal stage remapped: warp-per-row, lane l -> 4 consecutive cols
//     (c0 = 4*l). Two rows per warp = 2 independent slide chains per thread
//     (chains shorten 7 -> 3 steps); slide vb values come from registers
//     (they are init loads j=0..2), so only 14 LDS.128 per 4 points.
//   - XOR swizzle idx^((idx>>3)&3) makes the stride-4 float4 smem access
//     conflict-free (PITCH=136 keeps rows 128B-aligned).
//   - Lanes now hold consecutive columns of ONE row -> direct coalesced
//     float2 STG; the `so` staging tile + store pass are deleted.
//   - smem 17KB, 2 syncs/chunk, 7 CTAs/SM.

namespace {
constexpr int W = 512, H = 512;
constexpr int PAD = 5;                 // win=11 -> halo 5
constexpr int TX = 118;                // output cols per strip
constexpr int NSTRIP = 5;              // ceil(512/118)
constexpr int THREADS = 128;           // TX + 2*PAD
constexpr int RCHUNK = 8;              // rows staged in smem per iteration
constexpr int RBLOCK = 64;             // output rows per CTA
constexpr int NCHUNK = RBLOCK / RCHUNK;
constexpr int PITCH = 136;             // float4s per row; multiple of 8 -> rows 128B-aligned
constexpr float INV_N = 1.0f / 121.0f;
constexpr float COV = 121.0f / 120.0f;
}

__device__ __forceinline__ int swz(int idx) { return idx ^ ((idx >> 3) & 3); }

__device__ __forceinline__ float ld0(const float* __restrict__ p, int r, int gcol, bool cv) {
    if (cv && r >= 0 && r < H) return __ldg(p + r * W + gcol);
    return 0.0f;
}

__device__ __forceinline__ float ssim_pt(float hx, float hy, float hq, float hxy,
                                         float C1, float C2) {
    float ux  = hx  * INV_N;
    float uy  = hy  * INV_N;
    float uq  = hq  * INV_N;
    float uxy = hxy * INV_N;
    float uxux = ux * ux;
    float uyuy = uy * uy;
    float vxy = COV * (uxy - ux * uy);
    float A1 = 2.f * ux * uy + C1;
    float A2 = 2.f * vxy + C2;
    float B1 = uxux + uyuy + C1;
    float B2 = COV * (uq - uxux - uyuy) + C2;
    return __fdividef(A1 * A2, B1 * B2);
}

__global__ __launch_bounds__(THREADS, 7) void ssim_kernel(
    const float* __restrict__ img, const float* __restrict__ ref,
    const float* __restrict__ drange, float* __restrict__ out)
{
    __shared__ float4 vs4[RCHUNK][PITCH];    // (sx, sy, s(xx+yy), sxy), swizzled

    const int tid   = threadIdx.x;
    const int strip = blockIdx.x;
    const int rb    = blockIdx.y;
    const int b     = blockIdx.z;

    const float* ip = img + (size_t)b * H * W;
    const float* rp = ref + (size_t)b * H * W;
    float*       op = out + (size_t)b * H * W;

    const float dr = __ldg(drange + b);
    const float C1 = (0.01f * dr) * (0.01f * dr);
    const float C2 = (0.03f * dr) * (0.03f * dr);

    const int  gcol = strip * TX + tid - PAD;       // column this thread streams
    const bool cv   = (gcol >= 0) && (gcol < W);

    const int r_start = rb * RBLOCK;

    // --- init vertical running sums: rows [r_start-5, r_start+5] ---
    float sx = 0.f, sy = 0.f, sq = 0.f, sxy = 0.f;
    #pragma unroll
    for (int d = -PAD; d <= PAD; ++d) {
        float x = ld0(ip, r_start + d, gcol, cv);
        float y = ld0(rp, r_start + d, gcol, cv);
        sx += x; sy += y;
        sq  = fmaf(x, x, sq);
        sq  = fmaf(y, y, sq);
        sxy = fmaf(x, y, sxy);
    }

    const int lane = tid & 31;
    const int wrp  = tid >> 5;             // 0..3
    const int c0   = lane * 4;             // logical column base (0..124)
    const bool hact = (c0 < TX);           // lanes 30,31 idle in H
    const int gc   = strip * TX + c0;      // global column base
    const int swc  = swz(tid);             // swizzled index for V-stage store

    for (int ck = 0; ck < NCHUNK; ++ck) {
        const int r0 = r_start + ck * RCHUNK;

        // --- V(ck): stage 8 rows of packed vertical sums (swizzled) ---
        #pragma unroll
        for (int i = 0; i < RCHUNK; ++i) {
            vs4[i][swc] = make_float4(sx, sy, sq, sxy);
            const int r = r0 + i;
            float xn = ld0(ip, r + PAD + 1, gcol, cv);
            float yn = ld0(rp, r + PAD + 1, gcol, cv);
            float xo = ld0(ip, r - PAD, gcol, cv);        // L1 hit (loaded 11 rows ago)
            float yo = ld0(rp, r - PAD, gcol, cv);
            sx += xn - xo;
            sy += yn - yo;
            sq  += (xn * xn + yn * yn) - (xo * xo + yo * yo);
            sxy += xn * yn - xo * yo;
        }
        __syncthreads();

        // --- H(ck): 2 rows per warp, 4 points per lane, direct stores ---
        if (hact) {
            #pragma unroll
            for (int rr = 0; rr < 2; ++rr) {
                const int row = wrp * 2 + rr;
                const float4* __restrict__ vrow = vs4[row];

                // init window [c0, c0+10]; keep first 3 as slide subtrahends
                float4 v0 = vrow[swz(c0 + 0)];
                float4 v1 = vrow[swz(c0 + 1)];
                float4 v2 = vrow[swz(c0 + 2)];
                float hx = v0.x + v1.x + v2.x;
                float hy = v0.y + v1.y + v2.y;
                float hq = v0.z + v1.z + v2.z;
                float hxy = v0.w + v1.w + v2.w;
                #pragma unroll
                for (int j = 3; j < 11; ++j) {
                    float4 v = vrow[swz(c0 + j)];
                    hx += v.x; hy += v.y; hq += v.z; hxy += v.w;
                }

                float s0, s1, s2 = 0.f, s3 = 0.f;
                // k=0 (c0 < TX guaranteed; c0+1 <= 117 < TX always)
                s0 = ssim_pt(hx, hy, hq, hxy, C1, C2);
                {
                    float4 va = vrow[swz(c0 + 11)];
                    hx += va.x - v0.x; hy += va.y - v0.y;
                    hq += va.z - v0.z; hxy += va.w - v0.w;
                }
                // k=1
                s1 = ssim_pt(hx, hy, hq, hxy, C1, C2);
                if (c0 + 2 < TX) {
                    float4 va = vrow[swz(c0 + 12)];
                    hx += va.x - v1.x; hy += va.y - v1.y;
                    hq += va.z - v1.z; hxy += va.w - v1.w;
                    // k=2
                    s2 = ssim_pt(hx, hy, hq, hxy, C1, C2);
                    if (c0 + 3 < TX) {
                        float4 vb = vrow[swz(c0 + 13)];
                        hx += vb.x - v2.x; hy += vb.y - v2.y;
                        hq += vb.z - v2.z; hxy += vb.w - v2.w;
                        // k=3
                        s3 = ssim_pt(hx, hy, hq, hxy, C1, C2);
                    }
                }

                // direct coalesced stores: pairs are 8B-aligned (gc even)
                float* orow = op + (size_t)(r0 + row) * W;
                if (gc < W)
                    *reinterpret_cast<float2*>(orow + gc) = make_float2(s0, s1);
                if ((c0 + 2 < TX) && (gc + 2 < W))
                    *reinterpret_cast<float2*>(orow + gc + 2) = make_float2(s2, s3);
            }
        }
        __syncthreads();   // vs4 WAR: H done reading before next V writes
    }
}

extern "C" void kernel_launch(void* const* d_in, const int* in_sizes, int n_in,
                              void* d_out, int out_size) {
    const float* img = (const float*)d_in[0];
    const float* ref = (const float*)d_in[1];
    const float* dr  = (const float*)d_in[2];
    float* out = (float*)d_out;
    const int B = in_sizes[2];            // batch = data_range element count (64)
    dim3 grid(NSTRIP, H / RBLOCK, B);
    ssim_kernel<<<grid, THREADS>>>(img, ref, dr, out);
}